// round 3
// baseline (speedup 1.0000x reference)
#include <cuda_runtime.h>
#include <math.h>

#define DD 40
#define HH 40
#define WW 40
#define NVOX (DD*HH*WW)     // 64000
#define NB 2
#define KP 2048
#define EPSV 2.0f
#define BIGF 1e12f
#define NLINES (NB*DD*HH)   // 3200 lines per pass

// Scratch (no cudaMalloc allowed): ping-pong EDT buffers + accumulators
__device__ float  g_bufA[NB*NVOX];
__device__ float  g_bufB[NB*NVOX];
__device__ int    g_trueCount[NB];
__device__ int    g_predCount[NB];
__device__ double g_sum;
__device__ int    g_cnt;

__global__ void k_init() {
    if (threadIdx.x < NB) { g_trueCount[threadIdx.x] = 0; g_predCount[threadIdx.x] = 0; }
    if (threadIdx.x == 0) { g_sum = 0.0; g_cnt = 0; }
}

// 1-D brute-force squared-distance lower envelope: dst[i] = min_j f[j] + (i-j)^2
// 4-way split min chain to break the fmin dependency chain.
__device__ __forceinline__ void dt_line_regs(const float f[WW], float* __restrict__ dst,
                                             int base, int stride) {
    for (int i = 0; i < WW; i++) {
        float m0 = 4e12f, m1 = 4e12f, m2 = 4e12f, m3 = 4e12f;
        #pragma unroll
        for (int j = 0; j < WW; j += 4) {
            int d0 = i - j, d1 = i - j - 1, d2 = i - j - 2, d3 = i - j - 3;
            m0 = fminf(m0, f[j]   + (float)(d0*d0));
            m1 = fminf(m1, f[j+1] + (float)(d1*d1));
            m2 = fminf(m2, f[j+2] + (float)(d2*d2));
            m3 = fminf(m3, f[j+3] + (float)(d3*d3));
        }
        dst[base + i*stride] = fminf(fminf(m0, m1), fminf(m2, m3));
    }
}

// Pass X: seeds from target>0, lines along x (contiguous). Also counts trues & preds.
__global__ void k_passX(const float* __restrict__ inp, const float* __restrict__ tgt) {
    int l = blockIdx.x * blockDim.x + threadIdx.x;
    if (l >= NLINES) return;
    int b   = l / (DD*HH);
    int rem = l % (DD*HH);            // z*HH + y
    int base = b*NVOX + rem*WW;
    float f[WW];
    int tc = 0, pc = 0;
    #pragma unroll
    for (int x = 0; x < WW; x++) {
        float tv = tgt[base + x];
        bool t = (tv > 0.0f);
        tc += t ? 1 : 0;
        f[x] = t ? 0.0f : BIGF;
        pc += (inp[base + x] > EPSV) ? 1 : 0;
    }
    if (tc) atomicAdd(&g_trueCount[b], tc);
    if (pc) atomicAdd(&g_predCount[b], pc);
    dt_line_regs(f, g_bufA, base, 1);
}

// Pass Y: lines along y (stride WW), bufA -> bufB
__global__ void k_passY() {
    int l = blockIdx.x * blockDim.x + threadIdx.x;
    if (l >= NLINES) return;
    int b   = l / (DD*WW);
    int rem = l % (DD*WW);            // z*WW + x
    int z = rem / WW, x = rem % WW;
    int base = b*NVOX + z*HH*WW + x;
    float f[HH];
    #pragma unroll
    for (int j = 0; j < HH; j++) f[j] = g_bufA[base + j*WW];
    dt_line_regs(f, g_bufB, base, WW);
}

// Pass Z: lines along z (stride HH*WW), bufB -> bufA (final exact squared EDT)
__global__ void k_passZ() {
    int l = blockIdx.x * blockDim.x + threadIdx.x;
    if (l >= NLINES) return;
    int b   = l / (HH*WW);
    int rem = l % (HH*WW);            // y*WW + x
    int base = b*NVOX + rem;
    float f[DD];
    #pragma unroll
    for (int j = 0; j < DD; j++) f[j] = g_bufB[base + j*HH*WW];
    dt_line_regs(f, g_bufA, base, HH*WW);
}

// Fast-path reduction: when predCount[b] <= KP no ordering/cap is needed.
__global__ void k_reduce(const float* __restrict__ inp) {
    double lsum = 0.0; int lcnt = 0;
    for (int idx = blockIdx.x*blockDim.x + threadIdx.x; idx < NB*NVOX;
         idx += gridDim.x*blockDim.x) {
        int b = idx / NVOX;
        if (g_predCount[b] > KP) continue;        // handled by finalize fallback
        if (inp[idx] > EPSV) {
            lcnt++;
            if (g_trueCount[b] > 0)
                lsum += (double)sqrtf(fmaxf(g_bufA[idx], 0.0f));
        }
    }
    // warp reduce then one atomic per warp
    #pragma unroll
    for (int o = 16; o > 0; o >>= 1) {
        lsum += __shfl_down_sync(0xFFFFFFFFu, lsum, o);
        lcnt += __shfl_down_sync(0xFFFFFFFFu, lcnt, o);
    }
    if ((threadIdx.x & 31) == 0 && (lcnt > 0)) {
        atomicAdd(&g_sum, lsum);
        atomicAdd(&g_cnt, lcnt);
    }
}

// Finalize: (a) exact ordered-scan fallback for any batch with predCount > KP
// (first-2048-in-flat-order truncation, matching jnp.nonzero(size=KP));
// (b) write the mean. Launched with 1024 threads, 1 block.
__global__ void k_finalize(const float* __restrict__ inp, float* __restrict__ out) {
    __shared__ int warpSums[32];
    int lane = threadIdx.x & 31, wid = threadIdx.x >> 5;
    for (int b = 0; b < NB; b++) {
        if (g_predCount[b] <= KP) continue;       // fast path already covered it
        int runningBase = 0;
        double lsum = 0.0; int lcnt = 0;
        int tcnt = g_trueCount[b];
        for (int chunk = 0; chunk < NVOX; chunk += blockDim.x) {
            int idx = chunk + (int)threadIdx.x;
            bool pred = (idx < NVOX) && (inp[b*NVOX + idx] > EPSV);
            unsigned ball = __ballot_sync(0xFFFFFFFFu, pred);
            int lanePre = __popc(ball & ((1u << lane) - 1u));
            if (lane == 0) warpSums[wid] = __popc(ball);
            __syncthreads();
            int wOff = 0, total = 0;
            for (int w = 0; w < (int)(blockDim.x >> 5); w++) {
                int c = warpSums[w];
                if (w < wid) wOff += c;
                total += c;
            }
            int rank = runningBase + wOff + lanePre;
            if (pred && rank < KP) {
                lcnt++;
                if (tcnt > 0) lsum += (double)sqrtf(fmaxf(g_bufA[b*NVOX + idx], 0.0f));
            }
            runningBase += total;
            __syncthreads();
        }
        #pragma unroll
        for (int o = 16; o > 0; o >>= 1) {
            lsum += __shfl_down_sync(0xFFFFFFFFu, lsum, o);
            lcnt += __shfl_down_sync(0xFFFFFFFFu, lcnt, o);
        }
        if (lane == 0 && lcnt > 0) {
            atomicAdd(&g_sum, lsum);
            atomicAdd(&g_cnt, lcnt);
        }
    }
    __syncthreads();
    if (threadIdx.x == 0) {
        int c = g_cnt;
        out[0] = (c > 0) ? (float)(g_sum / (double)c) : 0.0f;
    }
}

extern "C" void kernel_launch(void* const* d_in, const int* in_sizes, int n_in,
                              void* d_out, int out_size) {
    const float* inp = (const float*)d_in[0];   // "input"  [2,40,40,40]
    const float* tgt = (const float*)d_in[1];   // "target" [2,40,40,40]
    float* out = (float*)d_out;

    const int lineThreads = 128;
    const int lineBlocks  = (NLINES + lineThreads - 1) / lineThreads;

    k_init<<<1, 32>>>();
    k_passX<<<lineBlocks, lineThreads>>>(inp, tgt);
    k_passY<<<lineBlocks, lineThreads>>>();
    k_passZ<<<lineBlocks, lineThreads>>>();
    k_reduce<<<128, 256>>>(inp);
    k_finalize<<<1, 1024>>>(inp, out);
}

// round 7
// speedup vs baseline: 1.0024x; 1.0024x over previous
#include <cuda_runtime.h>
#include <math.h>

#define DD    40
#define NVOX  64000          // 40*40*40
#define NB    2
#define KP    2048
#define EPSV  2.0f
#define BIGF  1e12f
#define SENT  1e9f           // sentinel threshold: real d2 <= 3*39^2 = 4563
#define NBLK  148
#define TPB   256
#define NCOL  3200           // per-pass 1-D lines: NB*40*40
#define NGRP  32000          // NCOL * 10  (4 outputs per thread)

// Scratch: 3 distinct buffers so every cross-phase read is a first-read
// (L1 cold -> fresh from L2; avoids stale-L1 hazards inside one launch).
__device__ float  g_A[NB*NVOX];
__device__ float  g_B[NB*NVOX];
__device__ float  g_C[NB*NVOX];
__device__ int    g_bar[4];          // rotating grid-barrier counters
__device__ double g_bsum[NB];
__device__ int    g_bcnt[NB];

// Grid barrier k (k=0..3). Reset-one-behind: after passing barrier k, block 0
// zeroes counter (k-1)&3. Reuse of that slot is >=2 barriers away (each of
// which block 0 must reach AFTER the reset), so the scheme is race-free and
// leaves the state correct for the next graph replay.
__device__ __forceinline__ void gbar(int k) {
    __syncthreads();
    if (threadIdx.x == 0) {
        __threadfence();
        atomicAdd(&g_bar[k], 1);
        volatile int* p = &g_bar[k];       // volatile -> bypasses L1
        while (*p < NBLK) { }
        if (blockIdx.x == 0) atomicExch(&g_bar[(k + 3) & 3], 0);
        __threadfence();
    }
    __syncthreads();
}

__global__ void __launch_bounds__(TPB, 1)
fused_kernel(const float* __restrict__ inp, const float* __restrict__ tgt,
             float* __restrict__ out) {
    const int tid = blockIdx.x * TPB + threadIdx.x;

    if (blockIdx.x == 0 && threadIdx.x == 0) {
        g_bsum[0] = 0.0; g_bsum[1] = 0.0;
        g_bcnt[0] = 0;   g_bcnt[1] = 0;
    }

    // ---- Pass X: seeds from target>0, lines along x (contiguous) -> g_A ----
    if (tid < NGRP) {
        int line = tid / 10;               // (b,z,y) flat, 0..3199
        int i0   = (tid - line * 10) * 4;  // 4 outputs i0..i0+3
        int base = line * DD;
        float m0 = 4e12f, m1 = 4e12f, m2 = 4e12f, m3 = 4e12f;
        #pragma unroll 8
        for (int j = 0; j < DD; j++) {
            float tv = tgt[base + j];
            float s  = (tv > 0.0f) ? 0.0f : BIGF;
            float d  = (float)(i0 - j);
            m0 = fminf(m0, fmaf(d,      d,      s));
            m1 = fminf(m1, fmaf(d+1.f,  d+1.f,  s));
            m2 = fminf(m2, fmaf(d+2.f,  d+2.f,  s));
            m3 = fminf(m3, fmaf(d+3.f,  d+3.f,  s));
        }
        *reinterpret_cast<float4*>(&g_A[base + i0]) = make_float4(m0, m1, m2, m3);
    }
    gbar(0);

    // ---- Pass Y: lines along y (stride 40), g_A -> g_B ----
    if (tid < NGRP) {
        int g = tid / NCOL;                // y-group 0..9
        int c = tid - g * NCOL;            // (b,z,x): adjacent threads -> adjacent x (coalesced)
        int b = c / 1600;
        int zx = c - b * 1600;
        int z = zx / DD, x = zx - z * DD;
        int colBase = b * NVOX + z * 1600 + x;
        int y0 = g * 4;
        float m0 = 4e12f, m1 = 4e12f, m2 = 4e12f, m3 = 4e12f;
        #pragma unroll 8
        for (int j = 0; j < DD; j++) {
            float v = g_A[colBase + j * DD];
            float d = (float)(y0 - j);
            m0 = fminf(m0, fmaf(d,      d,      v));
            m1 = fminf(m1, fmaf(d+1.f,  d+1.f,  v));
            m2 = fminf(m2, fmaf(d+2.f,  d+2.f,  v));
            m3 = fminf(m3, fmaf(d+3.f,  d+3.f,  v));
        }
        g_B[colBase + (y0    ) * DD] = m0;
        g_B[colBase + (y0 + 1) * DD] = m1;
        g_B[colBase + (y0 + 2) * DD] = m2;
        g_B[colBase + (y0 + 3) * DD] = m3;
    }
    gbar(1);

    // ---- Pass Z: lines along z (stride 1600), g_B -> g_C (final exact d^2) ----
    if (tid < NGRP) {
        int g = tid / NCOL;
        int c = tid - g * NCOL;            // (b,y,x)
        int b = c / 1600;
        int yx = c - b * 1600;
        int colBase = b * NVOX + yx;
        int z0 = g * 4;
        float m0 = 4e12f, m1 = 4e12f, m2 = 4e12f, m3 = 4e12f;
        #pragma unroll 8
        for (int j = 0; j < DD; j++) {
            float v = g_B[colBase + j * 1600];
            float d = (float)(z0 - j);
            m0 = fminf(m0, fmaf(d,      d,      v));
            m1 = fminf(m1, fmaf(d+1.f,  d+1.f,  v));
            m2 = fminf(m2, fmaf(d+2.f,  d+2.f,  v));
            m3 = fminf(m3, fmaf(d+3.f,  d+3.f,  v));
        }
        g_C[colBase + (z0    ) * 1600] = m0;
        g_C[colBase + (z0 + 1) * 1600] = m1;
        g_C[colBase + (z0 + 2) * 1600] = m2;
        g_C[colBase + (z0 + 3) * 1600] = m3;
    }
    gbar(2);

    // ---- Reduce: per-batch sum of 1-NN distances over pred voxels ----
    {
        double ls0 = 0.0, ls1 = 0.0;
        int lc0 = 0, lc1 = 0;
        for (int idx = tid; idx < NB * NVOX; idx += NBLK * TPB) {
            float v = inp[idx];
            if (v > EPSV) {
                float d2 = g_C[idx];
                float dist = (d2 > SENT) ? 0.0f : sqrtf(fmaxf(d2, 0.0f));
                if (idx < NVOX) { ls0 += (double)dist; lc0++; }
                else            { ls1 += (double)dist; lc1++; }
            }
        }
        #pragma unroll
        for (int o = 16; o > 0; o >>= 1) {
            ls0 += __shfl_down_sync(0xFFFFFFFFu, ls0, o);
            ls1 += __shfl_down_sync(0xFFFFFFFFu, ls1, o);
            lc0 += __shfl_down_sync(0xFFFFFFFFu, lc0, o);
            lc1 += __shfl_down_sync(0xFFFFFFFFu, lc1, o);
        }
        if ((threadIdx.x & 31) == 0) {
            if (lc0) { atomicAdd(&g_bsum[0], ls0); atomicAdd(&g_bcnt[0], lc0); }
            if (lc1) { atomicAdd(&g_bsum[1], ls1); atomicAdd(&g_bcnt[1], lc1); }
        }
    }
    gbar(3);

    // ---- Block 0: >KP ordered-truncation fallback (never taken in practice)
    //      + final mean write ----
    if (blockIdx.x == 0) {
        __shared__ int warpSums[8];
        __shared__ double rs[8];
        __shared__ int rc[8];
        int lane = threadIdx.x & 31, wid = threadIdx.x >> 5;

        for (int b = 0; b < NB; b++) {
            if (g_bcnt[b] <= KP) continue;   // fast path exact
            int runningBase = 0;
            double lsum = 0.0; int lcnt = 0;
            for (int chunk = 0; chunk < NVOX; chunk += TPB) {  // 64000 % 256 == 0
                int idx = chunk + (int)threadIdx.x;
                bool pred = inp[b * NVOX + idx] > EPSV;
                unsigned ball = __ballot_sync(0xFFFFFFFFu, pred);
                int lanePre = __popc(ball & ((1u << lane) - 1u));
                if (lane == 0) warpSums[wid] = __popc(ball);
                __syncthreads();
                int wOff = 0, total = 0;
                #pragma unroll
                for (int w = 0; w < 8; w++) {
                    int cc = warpSums[w];
                    if (w < wid) wOff += cc;
                    total += cc;
                }
                int rank = runningBase + wOff + lanePre;
                if (pred && rank < KP) {
                    lcnt++;
                    float d2 = g_C[b * NVOX + idx];
                    lsum += (d2 > SENT) ? 0.0 : (double)sqrtf(fmaxf(d2, 0.0f));
                }
                runningBase += total;
                __syncthreads();
            }
            #pragma unroll
            for (int o = 16; o > 0; o >>= 1) {
                lsum += __shfl_down_sync(0xFFFFFFFFu, lsum, o);
                lcnt += __shfl_down_sync(0xFFFFFFFFu, lcnt, o);
            }
            if (lane == 0) { rs[wid] = lsum; rc[wid] = lcnt; }
            __syncthreads();
            if (threadIdx.x == 0) {
                double s = 0.0; int cn = 0;
                for (int w = 0; w < 8; w++) { s += rs[w]; cn += rc[w]; }
                g_bsum[b] = s;       // overwrite (replaces fast-path value)
                g_bcnt[b] = cn;
            }
            __syncthreads();
        }

        if (threadIdx.x == 0) {
            int cnt = g_bcnt[0] + g_bcnt[1];
            double s = g_bsum[0] + g_bsum[1];
            out[0] = (cnt > 0) ? (float)(s / (double)cnt) : 0.0f;
        }
    }
}

extern "C" void kernel_launch(void* const* d_in, const int* in_sizes, int n_in,
                              void* d_out, int out_size) {
    const float* inp = (const float*)d_in[0];   // "input"  [2,40,40,40]
    const float* tgt = (const float*)d_in[1];   // "target" [2,40,40,40]
    float* out = (float*)d_out;
    fused_kernel<<<NBLK, TPB>>>(inp, tgt, out);
}

// round 11
// speedup vs baseline: 1.6098x; 1.6061x over previous
#include <cuda_runtime.h>
#include <math.h>

#define DD    40
#define SLAB  1600           // 40*40 slab elements
#define NVOX  64000          // 40*40*40
#define NB    2
#define KP    2048
#define EPSV  2.0f
#define BIGF  1e12f
#define SENT  1e9f           // real d2 <= 3*39^2 = 4563 << SENT << BIGF
#define NBLK  80             // one block per (b,z) slab
#define TPB   512
#define NTASK 400            // active tasks per block per phase (4 outputs each)

// Scratch (no cudaMalloc allowed)
__device__ float  g_B[NB*NVOX];   // after X+Y passes
__device__ float  g_C[NB*NVOX];   // final per-voxel 1-NN distance (fallback only)
__device__ int    g_bar0;         // single grid barrier counter
__device__ int    g_done;         // last-block ticket
__device__ double g_bsum[NB];
__device__ int    g_bcnt[NB];

__global__ void __launch_bounds__(TPB, 1)
fused_kernel(const float* __restrict__ inp, const float* __restrict__ tgt,
             float* __restrict__ out) {
    const int t = threadIdx.x;
    __shared__ float s0[SLAB];
    __shared__ float s1[SLAB];
    __shared__ double rs0[16], rs1[16];
    __shared__ int    rc0[16], rc1[16];
    __shared__ int    sIsLast;
    __shared__ int    warpSums[16];

    if (blockIdx.x == 0 && t == 0) {          // init accumulators (pre-barrier)
        g_bsum[0] = 0.0; g_bsum[1] = 0.0;
        g_bcnt[0] = 0;   g_bcnt[1] = 0;
    }

    // ================= Phase 1: per-slab pass X + pass Y =================
    const int b = blockIdx.x / DD;
    const int z = blockIdx.x - b * DD;
    const int slabBase = b * NVOX + z * SLAB;

    // seeds from target>0 (float4 loads, 400 threads cover 1600 floats)
    if (t < NTASK) {
        float4 v = reinterpret_cast<const float4*>(tgt + slabBase)[t];
        float4 s;
        s.x = (v.x > 0.0f) ? 0.0f : BIGF;
        s.y = (v.y > 0.0f) ? 0.0f : BIGF;
        s.z = (v.z > 0.0f) ? 0.0f : BIGF;
        s.w = (v.w > 0.0f) ? 0.0f : BIGF;
        reinterpret_cast<float4*>(s0)[t] = s;
    }
    __syncthreads();

    // pass X: rows along x, s0 -> s1
    if (t < NTASK) {
        int row = t / 10;                 // y
        int i0  = (t - row * 10) * 4;
        const float* f = s0 + row * DD;
        float m0 = 4e12f, m1 = 4e12f, m2 = 4e12f, m3 = 4e12f;
        #pragma unroll
        for (int j = 0; j < DD; j++) {
            float v = f[j];
            float d = (float)(i0 - j);
            m0 = fminf(m0, fmaf(d,       d,       v));
            m1 = fminf(m1, fmaf(d + 1.f, d + 1.f, v));
            m2 = fminf(m2, fmaf(d + 2.f, d + 2.f, v));
            m3 = fminf(m3, fmaf(d + 3.f, d + 3.f, v));
        }
        reinterpret_cast<float4*>(s1 + row * DD)[i0 >> 2] = make_float4(m0, m1, m2, m3);
    }
    __syncthreads();

    // pass Y: columns along y, s1 -> g_B  (lanes adjacent in x -> conflict-free
    // smem reads, coalesced global writes)
    if (t < NTASK) {
        int grp = t / DD;                 // y0/4
        int x   = t - grp * DD;
        int y0  = grp * 4;
        float m0 = 4e12f, m1 = 4e12f, m2 = 4e12f, m3 = 4e12f;
        #pragma unroll
        for (int j = 0; j < DD; j++) {
            float v = s1[j * DD + x];
            float d = (float)(y0 - j);
            m0 = fminf(m0, fmaf(d,       d,       v));
            m1 = fminf(m1, fmaf(d + 1.f, d + 1.f, v));
            m2 = fminf(m2, fmaf(d + 2.f, d + 2.f, v));
            m3 = fminf(m3, fmaf(d + 3.f, d + 3.f, v));
        }
        float* o = g_B + slabBase + x;
        o[(y0    ) * DD] = m0;
        o[(y0 + 1) * DD] = m1;
        o[(y0 + 2) * DD] = m2;
        o[(y0 + 3) * DD] = m3;
    }

    // =============== the only grid barrier (80 blocks) ===============
    __syncthreads();
    if (t == 0) {
        __threadfence();
        atomicAdd(&g_bar0, 1);
        volatile int* p = &g_bar0;
        while (*p < NBLK) { }
        __threadfence();
    }
    __syncthreads();

    // ============ Phase 2: pass Z fused with pred-reduction ============
    double ls0 = 0.0, ls1 = 0.0;
    int    lc0 = 0,   lc1 = 0;
    if (t < NTASK) {
        int t2 = blockIdx.x * NTASK + t;      // 0..31999
        int g  = t2 / 3200;                   // z-group
        int c  = t2 - g * 3200;               // b*1600 + y*40 + x
        int bb = c / SLAB;
        int yx = c - bb * SLAB;
        int colBase = bb * NVOX + yx;
        int z0 = g * 4;
        float m0 = 4e12f, m1 = 4e12f, m2 = 4e12f, m3 = 4e12f;
        #pragma unroll 8
        for (int j = 0; j < DD; j++) {
            float v = g_B[colBase + j * SLAB];
            float d = (float)(z0 - j);
            m0 = fminf(m0, fmaf(d,       d,       v));
            m1 = fminf(m1, fmaf(d + 1.f, d + 1.f, v));
            m2 = fminf(m2, fmaf(d + 2.f, d + 2.f, v));
            m3 = fminf(m3, fmaf(d + 3.f, d + 3.f, v));
        }
        float mv[4] = {m0, m1, m2, m3};
        #pragma unroll
        for (int k = 0; k < 4; k++) {
            int idx = colBase + (z0 + k) * SLAB;
            float d2 = mv[k];
            float dist = (d2 > SENT) ? 0.0f : sqrtf(fmaxf(d2, 0.0f));
            g_C[idx] = dist;                  // for >KP fallback only
            if (inp[idx] > EPSV) {
                if (bb == 0) { ls0 += (double)dist; lc0++; }
                else         { ls1 += (double)dist; lc1++; }
            }
        }
    }
    // block reduce (4 quantities)
    #pragma unroll
    for (int o = 16; o > 0; o >>= 1) {
        ls0 += __shfl_down_sync(0xFFFFFFFFu, ls0, o);
        ls1 += __shfl_down_sync(0xFFFFFFFFu, ls1, o);
        lc0 += __shfl_down_sync(0xFFFFFFFFu, lc0, o);
        lc1 += __shfl_down_sync(0xFFFFFFFFu, lc1, o);
    }
    int lane = t & 31, wid = t >> 5;
    if (lane == 0) { rs0[wid] = ls0; rs1[wid] = ls1; rc0[wid] = lc0; rc1[wid] = lc1; }
    __syncthreads();
    if (t == 0) {
        double a0 = 0.0, a1 = 0.0; int c0 = 0, c1 = 0;
        #pragma unroll
        for (int w = 0; w < 16; w++) { a0 += rs0[w]; a1 += rs1[w]; c0 += rc0[w]; c1 += rc1[w]; }
        if (c0) { atomicAdd(&g_bsum[0], a0); atomicAdd(&g_bcnt[0], c0); }
        if (c1) { atomicAdd(&g_bsum[1], a1); atomicAdd(&g_bcnt[1], c1); }
    }

    // ============ last-block ticket: fallback + finalize ============
    __threadfence();
    __syncthreads();
    if (t == 0) {
        int prev = atomicAdd(&g_done, 1);
        sIsLast = (prev == NBLK - 1) ? 1 : 0;
    }
    __syncthreads();
    if (!sIsLast) return;

    // >KP ordered-truncation fallback (first-2048-in-flat-order, matching
    // jnp.nonzero(size=KP)); never taken in practice but exact if it is.
    for (int bb = 0; bb < NB; bb++) {
        int cnt = *(volatile int*)&g_bcnt[bb];
        if (cnt <= KP) continue;
        int runningBase = 0;
        double lsum = 0.0; int lcnt = 0;
        for (int chunk = 0; chunk < NVOX; chunk += TPB) {   // 64000 % 512 == 0
            int idx = chunk + t;
            bool pred = inp[bb * NVOX + idx] > EPSV;
            unsigned ball = __ballot_sync(0xFFFFFFFFu, pred);
            int lanePre = __popc(ball & ((1u << lane) - 1u));
            if (lane == 0) warpSums[wid] = __popc(ball);
            __syncthreads();
            int wOff = 0, total = 0;
            #pragma unroll
            for (int w = 0; w < 16; w++) {
                int cc = warpSums[w];
                if (w < wid) wOff += cc;
                total += cc;
            }
            int rank = runningBase + wOff + lanePre;
            if (pred && rank < KP) {
                lcnt++;
                lsum += (double)g_C[bb * NVOX + idx];
            }
            runningBase += total;
            __syncthreads();
        }
        #pragma unroll
        for (int o = 16; o > 0; o >>= 1) {
            lsum += __shfl_down_sync(0xFFFFFFFFu, lsum, o);
            lcnt += __shfl_down_sync(0xFFFFFFFFu, lcnt, o);
        }
        if (lane == 0) { rs0[wid] = lsum; rc0[wid] = lcnt; }
        __syncthreads();
        if (t == 0) {
            double s = 0.0; int cn = 0;
            #pragma unroll
            for (int w = 0; w < 16; w++) { s += rs0[w]; cn += rc0[w]; }
            g_bsum[bb] = s;               // overwrite fast-path value
            g_bcnt[bb] = cn;
        }
        __syncthreads();
    }

    if (t == 0) {
        int    cnt = *(volatile int*)&g_bcnt[0] + *(volatile int*)&g_bcnt[1];
        double s   = g_bsum[0] + g_bsum[1];
        out[0] = (cnt > 0) ? (float)(s / (double)cnt) : 0.0f;
        g_done = 0;                       // reset for next graph replay
        g_bar0 = 0;
    }
}

extern "C" void kernel_launch(void* const* d_in, const int* in_sizes, int n_in,
                              void* d_out, int out_size) {
    const float* inp = (const float*)d_in[0];   // "input"  [2,40,40,40]
    const float* tgt = (const float*)d_in[1];   // "target" [2,40,40,40]
    float* out = (float*)d_out;
    fused_kernel<<<NBLK, TPB>>>(inp, tgt, out);
}

// round 12
// speedup vs baseline: 1.6129x; 1.0019x over previous
#include <cuda_runtime.h>
#include <math.h>

#define DD    40
#define SLAB  1600           // 40*40 slab elements
#define NVOX  64000          // 40*40*40
#define NB    2
#define KP    2048
#define EPSV  2.0f
#define BIGF  1e12f
#define SENT  1e9f           // real d2 <= 3*39^2 = 4563 << SENT << BIGF
#define NBLK  80             // one block per (b,z) slab
#define TPB   512
#define NTASK 400            // active tasks per block per phase (4 outputs each)

// Scratch (no cudaMalloc allowed)
__device__ float  g_B[NB*NVOX];   // after X+Y passes
__device__ float  g_C[NB*NVOX];   // final per-voxel 1-NN d^2 (fallback only)
__device__ int    g_done;         // last-block ticket for k2
__device__ double g_bsum[NB];
__device__ int    g_bcnt[NB];

// ======================= Kernel 1: slab X + Y passes =======================
__global__ void __launch_bounds__(TPB, 1)
k_passXY(const float* __restrict__ tgt) {
    const int t = threadIdx.x;
    __shared__ float s0[SLAB];
    __shared__ float s1[SLAB];

    if (blockIdx.x == 0 && t == 0) {      // init k2 accumulators (only k2 writes them)
        g_bsum[0] = 0.0; g_bsum[1] = 0.0;
        g_bcnt[0] = 0;   g_bcnt[1] = 0;
    }

    const int b = blockIdx.x / DD;
    const int z = blockIdx.x - b * DD;
    const int slabBase = b * NVOX + z * SLAB;

    // seeds from target>0 (float4 loads, 400 threads cover 1600 floats)
    if (t < NTASK) {
        float4 v = reinterpret_cast<const float4*>(tgt + slabBase)[t];
        float4 s;
        s.x = (v.x > 0.0f) ? 0.0f : BIGF;
        s.y = (v.y > 0.0f) ? 0.0f : BIGF;
        s.z = (v.z > 0.0f) ? 0.0f : BIGF;
        s.w = (v.w > 0.0f) ? 0.0f : BIGF;
        reinterpret_cast<float4*>(s0)[t] = s;
    }
    __syncthreads();

    // pass X: rows along x, s0 -> s1
    if (t < NTASK) {
        int row = t / 10;                 // y
        int i0  = (t - row * 10) * 4;
        const float* f = s0 + row * DD;
        float m0 = 4e12f, m1 = 4e12f, m2 = 4e12f, m3 = 4e12f;
        #pragma unroll
        for (int j = 0; j < DD; j++) {
            float v = f[j];
            float d = (float)(i0 - j);
            m0 = fminf(m0, fmaf(d,       d,       v));
            m1 = fminf(m1, fmaf(d + 1.f, d + 1.f, v));
            m2 = fminf(m2, fmaf(d + 2.f, d + 2.f, v));
            m3 = fminf(m3, fmaf(d + 3.f, d + 3.f, v));
        }
        reinterpret_cast<float4*>(s1 + row * DD)[i0 >> 2] = make_float4(m0, m1, m2, m3);
    }
    __syncthreads();

    // pass Y: columns along y, s1 -> g_B (conflict-free smem reads, coalesced writes)
    if (t < NTASK) {
        int grp = t / DD;                 // y0/4
        int x   = t - grp * DD;
        int y0  = grp * 4;
        float m0 = 4e12f, m1 = 4e12f, m2 = 4e12f, m3 = 4e12f;
        #pragma unroll
        for (int j = 0; j < DD; j++) {
            float v = s1[j * DD + x];
            float d = (float)(y0 - j);
            m0 = fminf(m0, fmaf(d,       d,       v));
            m1 = fminf(m1, fmaf(d + 1.f, d + 1.f, v));
            m2 = fminf(m2, fmaf(d + 2.f, d + 2.f, v));
            m3 = fminf(m3, fmaf(d + 3.f, d + 3.f, v));
        }
        float* o = g_B + slabBase + x;
        o[(y0    ) * DD] = m0;
        o[(y0 + 1) * DD] = m1;
        o[(y0 + 2) * DD] = m2;
        o[(y0 + 3) * DD] = m3;
    }
}

// ============ Kernel 2: Z pass + pred reduction + finalize ============
__global__ void __launch_bounds__(TPB, 1)
k_passZ_reduce(const float* __restrict__ inp, float* __restrict__ out) {
    const int t = threadIdx.x;
    __shared__ double rs0[16], rs1[16];
    __shared__ int    rc0[16], rc1[16];
    __shared__ int    sIsLast;
    __shared__ int    warpSums[16];
    int lane = t & 31, wid = t >> 5;

    double ls0 = 0.0, ls1 = 0.0;
    int    lc0 = 0,   lc1 = 0;
    if (t < NTASK) {
        int t2 = blockIdx.x * NTASK + t;      // 0..31999
        int g  = t2 / 3200;                   // z-group
        int c  = t2 - g * 3200;               // b*1600 + y*40 + x
        int bb = c / SLAB;
        int yx = c - bb * SLAB;
        int colBase = bb * NVOX + yx;
        int z0 = g * 4;
        float m0 = 4e12f, m1 = 4e12f, m2 = 4e12f, m3 = 4e12f;
        #pragma unroll 8
        for (int j = 0; j < DD; j++) {
            float v = g_B[colBase + j * SLAB];
            float d = (float)(z0 - j);
            m0 = fminf(m0, fmaf(d,       d,       v));
            m1 = fminf(m1, fmaf(d + 1.f, d + 1.f, v));
            m2 = fminf(m2, fmaf(d + 2.f, d + 2.f, v));
            m3 = fminf(m3, fmaf(d + 3.f, d + 3.f, v));
        }
        float mv[4] = {m0, m1, m2, m3};
        #pragma unroll
        for (int k = 0; k < 4; k++) {
            int idx = colBase + (z0 + k) * SLAB;
            float d2 = mv[k];
            g_C[idx] = d2;                    // raw d^2, for >KP fallback only
            if (inp[idx] > EPSV) {            // sqrt only on pred voxels (~1.5k/batch)
                float dist = (d2 > SENT) ? 0.0f : sqrtf(fmaxf(d2, 0.0f));
                if (bb == 0) { ls0 += (double)dist; lc0++; }
                else         { ls1 += (double)dist; lc1++; }
            }
        }
    }
    // block reduce
    #pragma unroll
    for (int o = 16; o > 0; o >>= 1) {
        ls0 += __shfl_down_sync(0xFFFFFFFFu, ls0, o);
        ls1 += __shfl_down_sync(0xFFFFFFFFu, ls1, o);
        lc0 += __shfl_down_sync(0xFFFFFFFFu, lc0, o);
        lc1 += __shfl_down_sync(0xFFFFFFFFu, lc1, o);
    }
    if (lane == 0) { rs0[wid] = ls0; rs1[wid] = ls1; rc0[wid] = lc0; rc1[wid] = lc1; }
    __syncthreads();
    if (t == 0) {
        double a0 = 0.0, a1 = 0.0; int c0 = 0, c1 = 0;
        #pragma unroll
        for (int w = 0; w < 16; w++) { a0 += rs0[w]; a1 += rs1[w]; c0 += rc0[w]; c1 += rc1[w]; }
        if (c0) { atomicAdd(&g_bsum[0], a0); atomicAdd(&g_bcnt[0], c0); }
        if (c1) { atomicAdd(&g_bsum[1], a1); atomicAdd(&g_bcnt[1], c1); }
    }

    // last-block ticket
    __threadfence();
    __syncthreads();
    if (t == 0) {
        int prev = atomicAdd(&g_done, 1);
        sIsLast = (prev == NBLK - 1) ? 1 : 0;
    }
    __syncthreads();
    if (!sIsLast) return;

    // >KP ordered-truncation fallback (first-2048-in-flat-order, matching
    // jnp.nonzero(size=KP)); never taken in practice but exact if it is.
    for (int bb = 0; bb < NB; bb++) {
        int cnt = *(volatile int*)&g_bcnt[bb];
        if (cnt <= KP) continue;
        int runningBase = 0;
        double lsum = 0.0; int lcnt = 0;
        for (int chunk = 0; chunk < NVOX; chunk += TPB) {   // 64000 % 512 == 0
            int idx = chunk + t;
            bool pred = inp[bb * NVOX + idx] > EPSV;
            unsigned ball = __ballot_sync(0xFFFFFFFFu, pred);
            int lanePre = __popc(ball & ((1u << lane) - 1u));
            if (lane == 0) warpSums[wid] = __popc(ball);
            __syncthreads();
            int wOff = 0, total = 0;
            #pragma unroll
            for (int w = 0; w < 16; w++) {
                int cc = warpSums[w];
                if (w < wid) wOff += cc;
                total += cc;
            }
            int rank = runningBase + wOff + lanePre;
            if (pred && rank < KP) {
                lcnt++;
                float d2 = g_C[bb * NVOX + idx];
                lsum += (d2 > SENT) ? 0.0 : (double)sqrtf(fmaxf(d2, 0.0f));
            }
            runningBase += total;
            __syncthreads();
        }
        #pragma unroll
        for (int o = 16; o > 0; o >>= 1) {
            lsum += __shfl_down_sync(0xFFFFFFFFu, lsum, o);
            lcnt += __shfl_down_sync(0xFFFFFFFFu, lcnt, o);
        }
        if (lane == 0) { rs0[wid] = lsum; rc0[wid] = lcnt; }
        __syncthreads();
        if (t == 0) {
            double s = 0.0; int cn = 0;
            #pragma unroll
            for (int w = 0; w < 16; w++) { s += rs0[w]; cn += rc0[w]; }
            g_bsum[bb] = s;               // overwrite fast-path value
            g_bcnt[bb] = cn;
        }
        __syncthreads();
    }

    if (t == 0) {
        int    cnt = *(volatile int*)&g_bcnt[0] + *(volatile int*)&g_bcnt[1];
        double s   = g_bsum[0] + g_bsum[1];
        out[0] = (cnt > 0) ? (float)(s / (double)cnt) : 0.0f;
        g_done = 0;                       // reset for next graph replay
    }
}

extern "C" void kernel_launch(void* const* d_in, const int* in_sizes, int n_in,
                              void* d_out, int out_size) {
    const float* inp = (const float*)d_in[0];   // "input"  [2,40,40,40]
    const float* tgt = (const float*)d_in[1];   // "target" [2,40,40,40]
    float* out = (float*)d_out;
    k_passXY<<<NBLK, TPB>>>(tgt);
    k_passZ_reduce<<<NBLK, TPB>>>(inp, out);
}